// round 2
// baseline (speedup 1.0000x reference)
#include <cuda_runtime.h>
#include <cuda_bf16.h>
#include <stdint.h>
#include <math.h>

#define NROWS 8192
#define HALF_N 4096
#define DDIM 256

// Scratch (allocation-free rule: __device__ globals)
__device__ __nv_bfloat16 g_repsA[NROWS * DDIM];  // normalized * 2*log2(e)
__device__ __nv_bfloat16 g_repsB[NROWS * DDIM];  // normalized
__device__ float g_spart[2][2][NROWS];           // [col-half][wn] per-row partial sum of 2^l2
__device__ float g_pos[NROWS];                   // positive logit (natural log domain)

static __device__ __forceinline__ float ex2f(float x) {
    float y;
    asm("ex2.approx.f32 %0, %1;" : "=f"(y) : "f"(x));
    return y;
}

static __device__ __forceinline__ void ldsm4(uint32_t& r0, uint32_t& r1,
                                             uint32_t& r2, uint32_t& r3, uint32_t addr) {
    asm volatile("ldmatrix.sync.aligned.m8n8.x4.shared.b16 {%0,%1,%2,%3}, [%4];"
                 : "=r"(r0), "=r"(r1), "=r"(r2), "=r"(r3) : "r"(addr));
}

static __device__ __forceinline__ void mma16816(float c[4], const uint32_t a[4],
                                                const uint32_t b[2]) {
    asm volatile(
        "mma.sync.aligned.m16n8k16.row.col.f32.bf16.bf16.f32 "
        "{%0,%1,%2,%3}, {%4,%5,%6,%7}, {%8,%9}, {%0,%1,%2,%3};"
        : "+f"(c[0]), "+f"(c[1]), "+f"(c[2]), "+f"(c[3])
        : "r"(a[0]), "r"(a[1]), "r"(a[2]), "r"(a[3]), "r"(b[0]), "r"(b[1]));
}

// ---------------------------------------------------------------------------
// Kernel 1: L2-normalize rows of [emb_i; emb_j], write bf16 (A scaled, B raw).
// One warp per row. 1024 blocks x 256 threads.
// ---------------------------------------------------------------------------
__global__ void k_norm(const float* __restrict__ ei, const float* __restrict__ ej) {
    const float C_SCALE = 2.8853900817779268f;  // 2 * log2(e)
    int row = blockIdx.x * 8 + (threadIdx.x >> 5);
    int lane = threadIdx.x & 31;
    const float* src = (row < HALF_N) ? (ei + (size_t)row * DDIM)
                                      : (ej + (size_t)(row - HALF_N) * DDIM);
    float4 v0 = ((const float4*)src)[lane * 2];
    float4 v1 = ((const float4*)src)[lane * 2 + 1];
    float ss = v0.x * v0.x + v0.y * v0.y + v0.z * v0.z + v0.w * v0.w
             + v1.x * v1.x + v1.y * v1.y + v1.z * v1.z + v1.w * v1.w;
#pragma unroll
    for (int o = 16; o > 0; o >>= 1) ss += __shfl_xor_sync(0xFFFFFFFFu, ss, o);
    float inv = 1.0f / fmaxf(sqrtf(ss), 1e-12f);
    float sa = inv * C_SCALE;

    __nv_bfloat162* pa = (__nv_bfloat162*)(g_repsA + (size_t)row * DDIM) + lane * 4;
    __nv_bfloat162* pb = (__nv_bfloat162*)(g_repsB + (size_t)row * DDIM) + lane * 4;
    pa[0] = __floats2bfloat162_rn(v0.x * sa, v0.y * sa);
    pa[1] = __floats2bfloat162_rn(v0.z * sa, v0.w * sa);
    pa[2] = __floats2bfloat162_rn(v1.x * sa, v1.y * sa);
    pa[3] = __floats2bfloat162_rn(v1.z * sa, v1.w * sa);
    pb[0] = __floats2bfloat162_rn(v0.x * inv, v0.y * inv);
    pb[1] = __floats2bfloat162_rn(v0.z * inv, v0.w * inv);
    pb[2] = __floats2bfloat162_rn(v1.x * inv, v1.y * inv);
    pb[3] = __floats2bfloat162_rn(v1.z * inv, v1.w * inv);
}

// ---------------------------------------------------------------------------
// Kernel 2: fused GEMM + exp + row-sum.
// grid (2, 64): x = column half (4096 cols), y = row block of 128.
// 256 threads = 8 warps; warp = 32 rows x 64 cols sub-tile of each 128x128 tile.
// smem: A tile 128x256 bf16 (64KB, swizzled) + B tile 128x256 bf16 (64KB).
// ---------------------------------------------------------------------------
__global__ void __launch_bounds__(256) k_main() {
    extern __shared__ unsigned char smem[];
    __nv_bfloat16* As = (__nv_bfloat16*)smem;
    __nv_bfloat16* Bs = (__nv_bfloat16*)(smem + 65536);

    const float LN2 = 0.6931471805599453f;

    int tid = threadIdx.x;
    int lane = tid & 31;
    int warp = tid >> 5;
    int wm = warp >> 1;   // 0..3 : row group of 32 within 128
    int wn = warp & 1;    // 0..1 : col group of 64 within 128
    int cb = blockIdx.x;  // column half
    int rb = blockIdx.y;  // row block
    int row0_cta = rb * 128;

    uint32_t As_base = (uint32_t)__cvta_generic_to_shared(As);
    uint32_t Bs_base = (uint32_t)__cvta_generic_to_shared(Bs);

    // Load A tile (once): 128 rows x 512B, 16B chunks, XOR-swizzled.
    {
        const uint4* src = (const uint4*)g_repsA + (size_t)row0_cta * 32;
        uint4* dst = (uint4*)As;
#pragma unroll
        for (int it = 0; it < 16; it++) {
            int idx = it * 256 + tid;
            int r = idx >> 5, c = idx & 31;
            dst[r * 32 + (c ^ (r & 7))] = src[idx];
        }
    }

    // ldmatrix lane address components
    int aRow0 = wm * 32 + (lane & 15);                      // + mt*16
    int aCo = lane >> 4;                                    // 16B chunk offset in k
    int bRowBase = wn * 64 + (lane & 7) + ((lane & 16) >> 1);  // + nb*16
    int bCo = (lane >> 3) & 1;

    float s[4] = {0.f, 0.f, 0.f, 0.f};

#pragma unroll 1
    for (int t = 0; t < 32; t++) {
        int ctile = cb * 4096 + t * 128;
        __syncthreads();  // previous tile's readers done
        {
            const uint4* src = (const uint4*)g_repsB + (size_t)ctile * 32;
            uint4* dst = (uint4*)Bs;
#pragma unroll
            for (int it = 0; it < 16; it++) {
                int idx = it * 256 + tid;
                int r = idx >> 5, c = idx & 31;
                dst[r * 32 + (c ^ (r & 7))] = src[idx];
            }
        }
        __syncthreads();

        float acc[2][8][4];
#pragma unroll
        for (int mt = 0; mt < 2; mt++)
#pragma unroll
            for (int nt = 0; nt < 8; nt++)
#pragma unroll
                for (int e = 0; e < 4; e++) acc[mt][nt][e] = 0.f;

#pragma unroll
        for (int ks = 0; ks < 16; ks++) {
            uint32_t a[2][4];
#pragma unroll
            for (int mt = 0; mt < 2; mt++) {
                int r = aRow0 + mt * 16;
                uint32_t addr = As_base + r * 512 + ((((ks * 2) + aCo) ^ (r & 7)) << 4);
                ldsm4(a[mt][0], a[mt][1], a[mt][2], a[mt][3], addr);
            }
            uint32_t b[8][2];
#pragma unroll
            for (int nb = 0; nb < 4; nb++) {
                int r = bRowBase + nb * 16;
                uint32_t addr = Bs_base + r * 512 + ((((ks * 2) + bCo) ^ (r & 7)) << 4);
                uint32_t r0, r1, r2, r3;
                ldsm4(r0, r1, r2, r3, addr);
                b[nb * 2][0] = r0; b[nb * 2][1] = r1;
                b[nb * 2 + 1][0] = r2; b[nb * 2 + 1][1] = r3;
            }
#pragma unroll
            for (int mt = 0; mt < 2; mt++)
#pragma unroll
                for (int nt = 0; nt < 8; nt++) mma16816(acc[mt][nt], a[mt], b[nt]);
        }

        // Epilogue: accumulate sum(2^l2) per row; handle diag mask + positive.
        int r0w = row0_cta + wm * 32;
        int c0w = ctile + wn * 64;
        bool hasdiag = ((unsigned)(r0w - c0w) < 64u);
        int pcol0 = (r0w + 4096) & 8191;
        bool haspos = ((unsigned)(pcol0 - c0w) < 64u);
        bool special = hasdiag || haspos;

#pragma unroll
        for (int mt = 0; mt < 2; mt++) {
            int rA = r0w + mt * 16 + (lane >> 2);
            int rB = rA + 8;
#pragma unroll
            for (int nt = 0; nt < 8; nt++) {
                float vx = acc[mt][nt][0], vy = acc[mt][nt][1];
                float vz = acc[mt][nt][2], vw = acc[mt][nt][3];
                int c = c0w + nt * 8 + (lane & 3) * 2;
                float e0 = ex2f(vx), e1 = ex2f(vy), e2 = ex2f(vz), e3 = ex2f(vw);
                if (special) {
                    if (c == rA) e0 = 0.f;
                    if (c + 1 == rA) e1 = 0.f;
                    if (c == rB) e2 = 0.f;
                    if (c + 1 == rB) e3 = 0.f;
                    int pA = (rA + 4096) & 8191;
                    int pB = (rB + 4096) & 8191;
                    if (c == pA) g_pos[rA] = vx * LN2;
                    if (c + 1 == pA) g_pos[rA] = vy * LN2;
                    if (c == pB) g_pos[rB] = vz * LN2;
                    if (c + 1 == pB) g_pos[rB] = vw * LN2;
                }
                s[mt * 2 + 0] += e0 + e1;
                s[mt * 2 + 1] += e2 + e3;
            }
        }
    }

    // Reduce partial sums across the 4 lanes sharing each row, store.
    // NOTE: warps (wm, wn=0) and (wm, wn=1) cover the SAME rows but different
    // column halves -> each writes its own wn slot (previous round's bug:
    // both wrote the same slot, halving the denominator => -ln2 loss shift).
#pragma unroll
    for (int i = 0; i < 4; i++) {
        s[i] += __shfl_xor_sync(0xFFFFFFFFu, s[i], 1);
        s[i] += __shfl_xor_sync(0xFFFFFFFFu, s[i], 2);
    }
    if ((lane & 3) == 0) {
        int r = row0_cta + wm * 32 + (lane >> 2);
        g_spart[cb][wn][r]      = s[0];
        g_spart[cb][wn][r + 8]  = s[1];
        g_spart[cb][wn][r + 16] = s[2];
        g_spart[cb][wn][r + 24] = s[3];
    }
}

// ---------------------------------------------------------------------------
// Kernel 3: final deterministic reduction -> scalar loss.
// log(sum 2^l2) == natural-log logsumexp of logits (base change folds out).
// ---------------------------------------------------------------------------
__global__ void k_reduce(float* __restrict__ out) {
    __shared__ float red[256];
    int tid = threadIdx.x;
    float a = 0.f;
    for (int r = tid; r < NROWS; r += 256) {
        float sden = g_spart[0][0][r] + g_spart[0][1][r]
                   + g_spart[1][0][r] + g_spart[1][1][r];
        a += logf(sden) - g_pos[r];
    }
    red[tid] = a;
    __syncthreads();
#pragma unroll
    for (int o = 128; o > 0; o >>= 1) {
        if (tid < o) red[tid] += red[tid + o];
        __syncthreads();
    }
    if (tid == 0) out[0] = red[0] * (1.0f / 8192.0f);
}

extern "C" void kernel_launch(void* const* d_in, const int* in_sizes, int n_in,
                              void* d_out, int out_size) {
    const float* ei = (const float*)d_in[0];
    const float* ej = (const float*)d_in[1];
    (void)in_sizes; (void)n_in; (void)out_size;

    cudaFuncSetAttribute(k_main, cudaFuncAttributeMaxDynamicSharedMemorySize, 131072);

    k_norm<<<1024, 256>>>(ei, ej);
    k_main<<<dim3(2, 64), 256, 131072>>>();
    k_reduce<<<1, 256>>>((float*)d_out);
}

// round 3
// speedup vs baseline: 1.2288x; 1.2288x over previous
#include <cuda_runtime.h>
#include <cuda_bf16.h>
#include <stdint.h>
#include <math.h>

#define NROWS 8192
#define HALF_N 4096
#define DDIM 256

// Scratch (allocation-free rule: __device__ globals)
__device__ __nv_bfloat16 g_repsA[NROWS * DDIM];  // normalized * 2*log2(e)
__device__ __nv_bfloat16 g_repsB[NROWS * DDIM];  // normalized
__device__ float g_spart[2][2][NROWS];           // [col-half][group] per-row partial sums
__device__ float g_pos[NROWS];                   // positive logit (natural log domain)
__device__ float g_rpart[32];
__device__ int g_sem;                            // zero-init; reset by last block each launch

static __device__ __forceinline__ float ex2f(float x) {
    float y;
    asm("ex2.approx.f32 %0, %1;" : "=f"(y) : "f"(x));
    return y;
}

static __device__ __forceinline__ void ldsm4(uint32_t& r0, uint32_t& r1,
                                             uint32_t& r2, uint32_t& r3, uint32_t addr) {
    asm volatile("ldmatrix.sync.aligned.m8n8.x4.shared.b16 {%0,%1,%2,%3}, [%4];"
                 : "=r"(r0), "=r"(r1), "=r"(r2), "=r"(r3) : "r"(addr));
}

static __device__ __forceinline__ void mma16816(float c[4], const uint32_t a[4],
                                                const uint32_t b[2]) {
    asm volatile(
        "mma.sync.aligned.m16n8k16.row.col.f32.bf16.bf16.f32 "
        "{%0,%1,%2,%3}, {%4,%5,%6,%7}, {%8,%9}, {%0,%1,%2,%3};"
        : "+f"(c[0]), "+f"(c[1]), "+f"(c[2]), "+f"(c[3])
        : "r"(a[0]), "r"(a[1]), "r"(a[2]), "r"(a[3]), "r"(b[0]), "r"(b[1]));
}

static __device__ __forceinline__ void cpasync16(uint32_t dst, const void* src) {
    asm volatile("cp.async.cg.shared.global [%0], [%1], 16;" :: "r"(dst), "l"(src));
}
#define CP_COMMIT() asm volatile("cp.async.commit_group;")
#define CP_WAIT1()  asm volatile("cp.async.wait_group 1;")
#define CP_WAIT0()  asm volatile("cp.async.wait_group 0;")
#define BAR_G(id)   asm volatile("bar.sync %0, 128;" :: "r"(id) : "memory")

// ---------------------------------------------------------------------------
// Kernel 1: L2-normalize rows; write bf16 (A scaled by 2*log2e, B raw).
// Two rows per warp (MLP=4). 512 blocks x 256 threads.
// ---------------------------------------------------------------------------
__global__ void k_norm(const float* __restrict__ ei, const float* __restrict__ ej) {
    const float C_SCALE = 2.8853900817779268f;  // 2 * log2(e)
    int warp = threadIdx.x >> 5;
    int lane = threadIdx.x & 31;
    int row0 = blockIdx.x * 16 + warp * 2;

#pragma unroll
    for (int rr = 0; rr < 2; rr++) {
        int row = row0 + rr;
        const float* src = (row < HALF_N) ? (ei + (size_t)row * DDIM)
                                          : (ej + (size_t)(row - HALF_N) * DDIM);
        float4 v0 = ((const float4*)src)[lane * 2];
        float4 v1 = ((const float4*)src)[lane * 2 + 1];
        float ss = v0.x * v0.x + v0.y * v0.y + v0.z * v0.z + v0.w * v0.w
                 + v1.x * v1.x + v1.y * v1.y + v1.z * v1.z + v1.w * v1.w;
#pragma unroll
        for (int o = 16; o > 0; o >>= 1) ss += __shfl_xor_sync(0xFFFFFFFFu, ss, o);
        float inv = 1.0f / fmaxf(sqrtf(ss), 1e-12f);
        float sa = inv * C_SCALE;

        __nv_bfloat162* pa = (__nv_bfloat162*)(g_repsA + (size_t)row * DDIM) + lane * 4;
        __nv_bfloat162* pb = (__nv_bfloat162*)(g_repsB + (size_t)row * DDIM) + lane * 4;
        pa[0] = __floats2bfloat162_rn(v0.x * sa, v0.y * sa);
        pa[1] = __floats2bfloat162_rn(v0.z * sa, v0.w * sa);
        pa[2] = __floats2bfloat162_rn(v1.x * sa, v1.y * sa);
        pa[3] = __floats2bfloat162_rn(v1.z * sa, v1.w * sa);
        pb[0] = __floats2bfloat162_rn(v0.x * inv, v0.y * inv);
        pb[1] = __floats2bfloat162_rn(v0.z * inv, v0.w * inv);
        pb[2] = __floats2bfloat162_rn(v1.x * inv, v1.y * inv);
        pb[3] = __floats2bfloat162_rn(v1.z * inv, v1.w * inv);
    }
}

// ---------------------------------------------------------------------------
// Kernel 2: fused GEMM + exp + row-sum.
// grid (2, 64): x = column half (4096 cols), y = row block of 128.
// 256 threads = 2 groups of 4 warps. Group g handles col-tiles t = g, g+2, ...
// Each group double-buffers its B tiles via cp.async and syncs with its OWN
// named barrier -> groups run phase-skewed, overlapping one group's MUFU
// epilogue with the other group's tensor work on the same SMSP.
// smem: A 128x256 bf16 (64KB, swizzled) + 4 x B 64x256 bf16 (32KB each).
// ---------------------------------------------------------------------------
__global__ void __launch_bounds__(256, 1) k_main() {
    extern __shared__ unsigned char smem[];
    const float LN2 = 0.6931471805599453f;

    int tid = threadIdx.x;
    int lane = tid & 31;
    int warp = tid >> 5;
    int wm = warp & 3;        // 0..3: 32-row group within 128 (one warp per SMSP per group)
    int g = warp >> 2;        // 0..1: phase group
    int tidg = tid & 127;     // thread id within group
    int cb = blockIdx.x;      // column half
    int rb = blockIdx.y;      // row block
    int row0_cta = rb * 128;

    uint32_t As_base = (uint32_t)__cvta_generic_to_shared(smem);
    uint32_t Bbuf[2];
    Bbuf[0] = As_base + 65536 + (g * 2 + 0) * 32768;
    Bbuf[1] = As_base + 65536 + (g * 2 + 1) * 32768;

    // ---- A tile (once, all 256 threads): 128 rows x 512B, swizzled cp.async
    {
        const uint4* src = (const uint4*)g_repsA + (size_t)row0_cta * 32;
#pragma unroll
        for (int it = 0; it < 16; it++) {
            int idx = it * 256 + tid;
            int r = idx >> 5, c = idx & 31;
            cpasync16(As_base + (r * 32 + (c ^ (r & 7))) * 16, src + idx);
        }
        CP_COMMIT();
    }

    // ---- prefetch this group's first two B tiles (t = g, g+2)
#pragma unroll
    for (int p = 0; p < 2; p++) {
        int t = g + 2 * p;
        const uint4* src = (const uint4*)g_repsB + (size_t)(cb * 4096 + t * 64) * 32;
#pragma unroll
        for (int it = 0; it < 16; it++) {
            int idx = it * 128 + tidg;
            int r = idx >> 5, c = idx & 31;
            cpasync16(Bbuf[p] + (r * 32 + (c ^ (r & 7))) * 16, src + idx);
        }
        CP_COMMIT();
    }
    CP_WAIT1();          // A + first B tile complete (second may be in flight)
    __syncthreads();     // A visible to everyone; groups decouple after this

    // ldmatrix lane address components
    int aRow0 = wm * 32 + (lane & 15);
    int aCo = lane >> 4;
    int bRowBase = (lane & 7) + ((lane & 16) >> 1);
    int bCo = (lane >> 3) & 1;

    float s[4] = {0.f, 0.f, 0.f, 0.f};

#pragma unroll 1
    for (int i = 0; i < 32; i++) {
        int t = g + 2 * i;
        int ctile = cb * 4096 + t * 64;
        uint32_t Bs_base = Bbuf[i & 1];

        float acc[2][8][4];
#pragma unroll
        for (int mt = 0; mt < 2; mt++)
#pragma unroll
            for (int nt = 0; nt < 8; nt++)
#pragma unroll
                for (int e = 0; e < 4; e++) acc[mt][nt][e] = 0.f;

#pragma unroll
        for (int ks = 0; ks < 16; ks++) {
            uint32_t a[2][4];
#pragma unroll
            for (int mt = 0; mt < 2; mt++) {
                int r = aRow0 + mt * 16;
                uint32_t addr = As_base + r * 512 + ((((ks * 2) + aCo) ^ (r & 7)) << 4);
                ldsm4(a[mt][0], a[mt][1], a[mt][2], a[mt][3], addr);
            }
            uint32_t b[8][2];
#pragma unroll
            for (int nb = 0; nb < 4; nb++) {
                int r = bRowBase + nb * 16;
                uint32_t addr = Bs_base + r * 512 + ((((ks * 2) + bCo) ^ (r & 7)) << 4);
                uint32_t r0, r1, r2, r3;
                ldsm4(r0, r1, r2, r3, addr);
                b[nb * 2][0] = r0; b[nb * 2][1] = r1;
                b[nb * 2 + 1][0] = r2; b[nb * 2 + 1][1] = r3;
            }
#pragma unroll
            for (int mt = 0; mt < 2; mt++)
#pragma unroll
                for (int nt = 0; nt < 8; nt++) mma16816(acc[mt][nt], a[mt], b[nt]);
        }

        // Epilogue: accumulate sum(2^l2) per row; diag mask + positive capture.
        int r0w = row0_cta + wm * 32;
        int c0w = ctile;
        bool hasdiag = ((unsigned)(r0w - c0w) < 64u);
        int pcol0 = (r0w + 4096) & 8191;
        bool haspos = ((unsigned)(pcol0 - c0w) < 64u);
        bool special = hasdiag || haspos;

#pragma unroll
        for (int mt = 0; mt < 2; mt++) {
            int rA = r0w + mt * 16 + (lane >> 2);
            int rB = rA + 8;
#pragma unroll
            for (int nt = 0; nt < 8; nt++) {
                float vx = acc[mt][nt][0], vy = acc[mt][nt][1];
                float vz = acc[mt][nt][2], vw = acc[mt][nt][3];
                int c = c0w + nt * 8 + (lane & 3) * 2;
                float e0 = ex2f(vx), e1 = ex2f(vy), e2 = ex2f(vz), e3 = ex2f(vw);
                if (special) {
                    if (c == rA) e0 = 0.f;
                    if (c + 1 == rA) e1 = 0.f;
                    if (c == rB) e2 = 0.f;
                    if (c + 1 == rB) e3 = 0.f;
                    int pA = (rA + 4096) & 8191;
                    int pB = (rB + 4096) & 8191;
                    if (c == pA) g_pos[rA] = vx * LN2;
                    if (c + 1 == pA) g_pos[rA] = vy * LN2;
                    if (c == pB) g_pos[rB] = vz * LN2;
                    if (c + 1 == pB) g_pos[rB] = vw * LN2;
                }
                s[mt * 2 + 0] += e0 + e1;
                s[mt * 2 + 1] += e2 + e3;
            }
        }

        // Pipeline: refill the buffer just consumed with tile t+4.
        BAR_G(g + 1);                      // whole group done reading buf[i&1]
        if (i < 30) {
            int tn = t + 4;
            const uint4* src = (const uint4*)g_repsB + (size_t)(cb * 4096 + tn * 64) * 32;
#pragma unroll
            for (int it = 0; it < 16; it++) {
                int idx = it * 128 + tidg;
                int r = idx >> 5, c = idx & 31;
                cpasync16(Bbuf[i & 1] + (r * 32 + (c ^ (r & 7))) * 16, src + idx);
            }
            CP_COMMIT();
            CP_WAIT1();                    // next buffer's fill (mine) complete
        } else {
            CP_WAIT0();
        }
        BAR_G(g + 1);                      // everyone's fill visible
    }

    // Reduce partial sums across the 4 lanes sharing each row, store per group.
#pragma unroll
    for (int i = 0; i < 4; i++) {
        s[i] += __shfl_xor_sync(0xFFFFFFFFu, s[i], 1);
        s[i] += __shfl_xor_sync(0xFFFFFFFFu, s[i], 2);
    }
    if ((lane & 3) == 0) {
        int r = row0_cta + wm * 32 + (lane >> 2);
        g_spart[cb][g][r]      = s[0];
        g_spart[cb][g][r + 8]  = s[1];
        g_spart[cb][g][r + 16] = s[2];
        g_spart[cb][g][r + 24] = s[3];
    }
}

// ---------------------------------------------------------------------------
// Kernel 3: final reduction -> scalar loss. 32 blocks; the last block to
// finish sums the 32 partials in a FIXED order (deterministic) and resets
// the semaphore for the next graph replay.
// ---------------------------------------------------------------------------
__global__ void k_reduce(float* __restrict__ out) {
    __shared__ float red[256];
    __shared__ int isLast;
    int tid = threadIdx.x;
    int r = blockIdx.x * 256 + tid;
    float sden = g_spart[0][0][r] + g_spart[0][1][r]
               + g_spart[1][0][r] + g_spart[1][1][r];
    red[tid] = logf(sden) - g_pos[r];
    __syncthreads();
#pragma unroll
    for (int o = 128; o > 0; o >>= 1) {
        if (tid < o) red[tid] += red[tid + o];
        __syncthreads();
    }
    if (tid == 0) {
        g_rpart[blockIdx.x] = red[0];
        __threadfence();
        int old = atomicAdd(&g_sem, 1);
        isLast = (old == 31);
    }
    __syncthreads();
    if (tid == 0 && isLast) {
        __threadfence();
        volatile float* rp = g_rpart;
        float a = 0.f;
        for (int i = 0; i < 32; i++) a += rp[i];
        out[0] = a * (1.0f / 8192.0f);
        g_sem = 0;
    }
}

extern "C" void kernel_launch(void* const* d_in, const int* in_sizes, int n_in,
                              void* d_out, int out_size) {
    const float* ei = (const float*)d_in[0];
    const float* ej = (const float*)d_in[1];
    (void)in_sizes; (void)n_in; (void)out_size;

    cudaFuncSetAttribute(k_main, cudaFuncAttributeMaxDynamicSharedMemorySize, 196608);

    k_norm<<<512, 256>>>(ei, ej);
    k_main<<<dim3(2, 64), 256, 196608>>>();
    k_reduce<<<32, 256>>>((float*)d_out);
}